// round 15
// baseline (speedup 1.0000x reference)
#include <cuda_runtime.h>
#include <cuda_fp16.h>
#include <cstdint>

// ---------------------------------------------------------------------------
// Problem shape (fixed by the dataset)
// ---------------------------------------------------------------------------
#define BB 8
#define MM 2048
#define NN 2048
#define KK 2048
#define T64 64
#define MT 32
#define KT 32
#define THRESH 1e-6f

// ---------------------------------------------------------------------------
// Scratch (device globals — no allocation allowed)
//   Single-product fp16: A -> fp16 RN (masked), B -> fp16 RN (transposed).
//   Quadrature error model validated: R9 2.08e-4 (B only), R11-R14 2.94e-4.
// ---------------------------------------------------------------------------
__device__ __half g_Ah[(size_t)BB * MM * KK];   // [b][m][k]
__device__ __half g_Bh[(size_t)BB * NN * KK];   // transposed: [b][n][k]

// ---------------------------------------------------------------------------
// Helpers
// ---------------------------------------------------------------------------
__device__ __forceinline__ uint32_t smem_u32(const void* p) {
    uint32_t a;
    asm("{ .reg .u64 t; cvta.to.shared.u64 t, %1; cvt.u32.u64 %0, t; }" : "=r"(a) : "l"(p));
    return a;
}
__device__ __forceinline__ void cp16(uint32_t dst, const void* src) {
    asm volatile("cp.async.cg.shared.global [%0], [%1], 16;" :: "r"(dst), "l"(src));
}
// 128-byte-row swizzle (SW128): XOR bits[6:4] with bits [9:7]
#define SMEM_SWIZZLE_128B(off) ((off) ^ (((off) >> 3) & 0x70))

__device__ __forceinline__ void ldsm_x4(uint32_t r[4], uint32_t addr) {
    asm volatile("ldmatrix.sync.aligned.m8n8.x4.shared.b16 {%0,%1,%2,%3}, [%4];"
                 : "=r"(r[0]), "=r"(r[1]), "=r"(r[2]), "=r"(r[3]) : "r"(addr));
}
__device__ __forceinline__ void mma_f16(float c[4], const uint32_t a[4],
                                        uint32_t b0, uint32_t b1) {
    asm volatile(
        "mma.sync.aligned.m16n8k16.row.col.f32.f16.f16.f32 "
        "{%0,%1,%2,%3}, {%4,%5,%6,%7}, {%8,%9}, {%0,%1,%2,%3};"
        : "+f"(c[0]), "+f"(c[1]), "+f"(c[2]), "+f"(c[3])
        : "r"(a[0]), "r"(a[1]), "r"(a[2]), "r"(a[3]), "r"(b0), "r"(b1));
}

// ---------------------------------------------------------------------------
// Kernel 1: fused activity prescan + A conversion (single fp16 RN).
// ---------------------------------------------------------------------------
__global__ __launch_bounds__(256)
void convA_fused_kernel(const float* __restrict__ a) {
    const int tile = blockIdx.x;
    const int b    = tile / (MT * KT);
    const int rem  = tile % (MT * KT);
    const int mt   = rem / KT;
    const int kt   = rem % KT;
    const size_t gbase = ((size_t)b * MM + (size_t)mt * T64) * KK + (size_t)kt * T64;
    const float* base = a + gbase;

    const int r0 = threadIdx.x >> 4;          // 0..15
    const int c0 = (threadIdx.x & 15) * 4;    // 0..60

    float4 v[4];
    float mx = 0.0f;
    #pragma unroll
    for (int j = 0; j < 4; j++) {
        v[j] = *reinterpret_cast<const float4*>(base + (size_t)(r0 + j * 16) * KK + c0);
        mx = fmaxf(mx, fmaxf(fmaxf(fabsf(v[j].x), fabsf(v[j].y)),
                             fmaxf(fabsf(v[j].z), fabsf(v[j].w))));
    }
    #pragma unroll
    for (int off = 16; off > 0; off >>= 1)
        mx = fmaxf(mx, __shfl_xor_sync(0xFFFFFFFFu, mx, off));

    __shared__ float s[8];
    __shared__ float s_msk;
    if ((threadIdx.x & 31) == 0) s[threadIdx.x >> 5] = mx;
    __syncthreads();
    if (threadIdx.x == 0) {
        float m = s[0];
        #pragma unroll
        for (int w = 1; w < 8; w++) m = fmaxf(m, s[w]);
        s_msk = (m > THRESH) ? 1.0f : 0.0f;
    }
    __syncthreads();
    const float msk = s_msk;

    #pragma unroll
    for (int j = 0; j < 4; j++) {
        unsigned short hb[4];
        hb[0] = __half_as_ushort(__float2half_rn(v[j].x * msk));
        hb[1] = __half_as_ushort(__float2half_rn(v[j].y * msk));
        hb[2] = __half_as_ushort(__float2half_rn(v[j].z * msk));
        hb[3] = __half_as_ushort(__float2half_rn(v[j].w * msk));
        const size_t o = gbase + (size_t)(r0 + j * 16) * KK + c0;
        *reinterpret_cast<ushort4*>(g_Ah + o) = make_ushort4(hb[0], hb[1], hb[2], hb[3]);
    }
}

// ---------------------------------------------------------------------------
// Kernel 2: convert + transpose B: fp32 [b][k][n] -> fp16 [b][n][k]
//   64x64 tiles, 4x float4 loads + 4x ushort4 stores per thread (MLP 4).
// ---------------------------------------------------------------------------
__global__ __launch_bounds__(256)
void convB_kernel(const float* __restrict__ Bsrc) {
    __shared__ float t[64][65];
    const int b  = blockIdx.z;
    const int n0 = blockIdx.x * 64;
    const int k0 = blockIdx.y * 64;
    const int tid = threadIdx.x;

    {
        const int r  = tid >> 4;            // 0..15 (k-row base)
        const int c4 = (tid & 15) * 4;      // n offset
        const float* src = Bsrc + (size_t)b * KK * NN + (size_t)k0 * NN + n0;
        #pragma unroll
        for (int j = 0; j < 4; j++) {
            const float4 v = *reinterpret_cast<const float4*>(src + (size_t)(r + j * 16) * NN + c4);
            t[r + j * 16][c4 + 0] = v.x; t[r + j * 16][c4 + 1] = v.y;
            t[r + j * 16][c4 + 2] = v.z; t[r + j * 16][c4 + 3] = v.w;
        }
    }
    __syncthreads();

    const int n  = tid >> 2;                // 0..63
    const int kq = (tid & 3) * 16;          // 0, 16, 32, 48
    __half* dst = g_Bh + (size_t)b * NN * KK + (size_t)(n0 + n) * KK + k0 + kq;
    #pragma unroll
    for (int g = 0; g < 4; g++) {
        unsigned short hb[4];
        #pragma unroll
        for (int j = 0; j < 4; j++)
            hb[j] = __half_as_ushort(__float2half_rn(t[kq + g * 4 + j][n]));
        *reinterpret_cast<ushort4*>(dst + g * 4) = make_ushort4(hb[0], hb[1], hb[2], hb[3]);
    }
}

// ---------------------------------------------------------------------------
// Kernel 3: single-product fp16 GEMM via mma.sync (m16n8k16).
//   CTA tile 128(M) x 128(N), K-chunk 64, 8 warps (2x4), warp tile 64x32.
//   3 slots / prefetch-depth-2 cp.async pipeline, one barrier per iteration.
//   NEW: register double-buffered fragments — LDSMs for step ks+1 fly under
//   the MMA burst of step ks; post-barrier stall happens once per chunk.
// ---------------------------------------------------------------------------
#define GM 128
#define GN 128
#define GK 64
#define KCHUNKS (KK / GK)            // 32
#define NSTAGE 3

// Stage layout (SW128-swizzled 128-byte rows): AH [128][128B], BH [128][128B]
#define OFF_AH 0
#define OFF_BH 16384
#define STAGE_BYTES 32768            // 32 KB
#define GEMM_SMEM (NSTAGE * STAGE_BYTES)  // 96 KB

__device__ __forceinline__ void load_stage(uint32_t sbase,
                                           const __half* Ah, const __half* Bh,
                                           int k0, int tid) {
    #pragma unroll
    for (int t = 0; t < 4; t++) {
        const int c = tid + t * 256;
        const int r = c >> 3, kc = c & 7;
        const uint32_t off = SMEM_SWIZZLE_128B((uint32_t)(r * 128 + kc * 16));
        const size_t gofs = (size_t)r * KK + k0 + kc * 8;    // fp16 elements
        cp16(sbase + OFF_AH + off, Ah + gofs);
        cp16(sbase + OFF_BH + off, Bh + gofs);
    }
}

__global__ __launch_bounds__(256, 2)
void gemm_kernel(float* __restrict__ C) {
    extern __shared__ __align__(1024) char smem[];
    const uint32_t sb = smem_u32(smem);
    const int tid  = threadIdx.x;
    const int wid  = tid >> 5;
    const int lane = tid & 31;
    const int wm   = wid >> 2;           // 0..1  -> m offset wm*64
    const int wn   = wid & 3;            // 0..3  -> n offset wn*32
    const int b  = blockIdx.z;
    const int m0 = blockIdx.y * GM;
    const int n0 = blockIdx.x * GN;

    const __half* Ah = g_Ah + (size_t)b * MM * KK + (size_t)m0 * KK;
    const __half* Bh = g_Bh + (size_t)b * NN * KK + (size_t)n0 * KK;

    float acc[4][4][4];                  // [m-tile][n-tile][frag]
    #pragma unroll
    for (int i = 0; i < 4; i++)
        #pragma unroll
        for (int j = 0; j < 4; j++)
            #pragma unroll
            for (int r = 0; r < 4; r++) acc[i][j][r] = 0.0f;

    const int lrow = lane & 15;
    const uint32_t lh16 = (uint32_t)(lane >> 4) * 16;   // 0 or 16

    // Per-thread swizzled base offsets (bytecol folds in via XOR: the SW128
    // mask only touches bits [6:4], and row*128 has zero low bits, so
    // SWZ(row*128 + bc) == SWZ(row*128) ^ bc for bc < 128).
    uint32_t baseA[4], baseB[2];
    #pragma unroll
    for (int mt = 0; mt < 4; mt++)
        baseA[mt] = OFF_AH + SMEM_SWIZZLE_128B((uint32_t)((wm * 64 + mt * 16 + lrow) * 128));
    #pragma unroll
    for (int nt2 = 0; nt2 < 2; nt2++)
        baseB[nt2] = OFF_BH + SMEM_SWIZZLE_128B((uint32_t)((wn * 32 + nt2 * 16 + lrow) * 128));

    // prologue: prefetch depth 2 (chunks 0 and 1 into slots 0 and 1)
    load_stage(sb + 0 * STAGE_BYTES, Ah, Bh, 0 * GK, tid);
    asm volatile("cp.async.commit_group;" ::: "memory");
    load_stage(sb + 1 * STAGE_BYTES, Ah, Bh, 1 * GK, tid);
    asm volatile("cp.async.commit_group;" ::: "memory");

    uint32_t ah[2][4][4], bbf[2][2][4];  // double-buffered fragments

    int stage = 0;           // slot of chunk `it`   (chunk c -> slot c % 3)
    int fill  = 2;           // slot for chunk `it+2`
    for (int it = 0; it < KCHUNKS; it++) {
        const uint32_t sbase = sb + stage * STAGE_BYTES;

        if (it + 2 < KCHUNKS) asm volatile("cp.async.wait_group 1;" ::: "memory");
        else                  asm volatile("cp.async.wait_group 0;" ::: "memory");
        __syncthreads();

        // preload fragments for ks = 0
        {
            const uint32_t bc = lh16;
            #pragma unroll
            for (int mt = 0; mt < 4; mt++)  ldsm_x4(ah[0][mt],  sbase + (baseA[mt]  ^ bc));
            #pragma unroll
            for (int nt2 = 0; nt2 < 2; nt2++) ldsm_x4(bbf[0][nt2], sbase + (baseB[nt2] ^ bc));
        }

        #pragma unroll
        for (int ks = 0; ks < 4; ks++) {     // 4 x k16 steps per 64-chunk
            const int cur = ks & 1, nxt = cur ^ 1;

            // issue next step's LDSMs first — they retire under the MMA burst
            if (ks < 3) {
                const uint32_t bc = (uint32_t)((ks + 1) * 32) + lh16;
                #pragma unroll
                for (int mt = 0; mt < 4; mt++)  ldsm_x4(ah[nxt][mt],  sbase + (baseA[mt]  ^ bc));
                #pragma unroll
                for (int nt2 = 0; nt2 < 2; nt2++) ldsm_x4(bbf[nxt][nt2], sbase + (baseB[nt2] ^ bc));
            }

            // 16 MMAs on the current buffer, 16 distinct accumulators
            #pragma unroll
            for (int mt = 0; mt < 4; mt++)
                #pragma unroll
                for (int nt2 = 0; nt2 < 2; nt2++) {
                    mma_f16(acc[mt][nt2 * 2 + 0], ah[cur][mt], bbf[cur][nt2][0], bbf[cur][nt2][2]);
                    mma_f16(acc[mt][nt2 * 2 + 1], ah[cur][mt], bbf[cur][nt2][1], bbf[cur][nt2][3]);
                }
        }

        // refill AFTER compute (safety proven by this iteration's top barrier)
        if (it + 2 < KCHUNKS) {
            load_stage(sb + fill * STAGE_BYTES, Ah, Bh, (it + 2) * GK, tid);
            asm volatile("cp.async.commit_group;" ::: "memory");
        }

        stage = (stage + 1 == NSTAGE) ? 0 : stage + 1;
        fill  = (fill  + 1 == NSTAGE) ? 0 : fill  + 1;
    }

    // epilogue: c frag -> rows (lane>>2) and +8, cols (lane&3)*2..+1
    const int crow0 = m0 + wm * 64 + (lane >> 2);
    const int ccol0 = n0 + wn * 32 + (lane & 3) * 2;
    float* Cb = C + (size_t)b * MM * NN;
    #pragma unroll
    for (int mt = 0; mt < 4; mt++) {
        #pragma unroll
        for (int nt = 0; nt < 4; nt++) {
            float* p0 = Cb + (size_t)(crow0 + mt * 16) * NN + ccol0 + nt * 8;
            float* p1 = p0 + 8 * NN;
            *reinterpret_cast<float2*>(p0) = make_float2(acc[mt][nt][0], acc[mt][nt][1]);
            *reinterpret_cast<float2*>(p1) = make_float2(acc[mt][nt][2], acc[mt][nt][3]);
        }
    }
}

// ---------------------------------------------------------------------------
// Launch
// ---------------------------------------------------------------------------
extern "C" void kernel_launch(void* const* d_in, const int* in_sizes, int n_in,
                              void* d_out, int out_size) {
    const float* a = (const float*)d_in[0];
    const float* bsrc = (const float*)d_in[1];
    float* out = (float*)d_out;

    cudaFuncSetAttribute(gemm_kernel, cudaFuncAttributeMaxDynamicSharedMemorySize, GEMM_SMEM);

    convA_fused_kernel<<<BB * MT * KT, 256>>>(a);
    dim3 gb(NN / 64, KK / 64, BB);          // (32, 32, 8)
    convB_kernel<<<gb, 256>>>(bsrc);
    dim3 gg(NN / GN, MM / GM, BB);          // (16, 16, 8)
    gemm_kernel<<<gg, 256, GEMM_SMEM>>>(out);
}